// round 2
// baseline (speedup 1.0000x reference)
#include <cuda_runtime.h>
#include <cuda_bf16.h>

#define CIN 512
#define COUT 512
#define HH 64
#define WW 64
#define BB 8
#define SS 512

#define TILE 16
#define COB 64
#define CCH 8
#define XSTR 19   // odd stride -> max 2-way bank conflicts on scalar x loads

// Scratch (device globals: allocation-free rule)
__device__ float g_s[BB * CIN];          // modulation scales
__device__ float g_wsq[COUT * CIN];      // sum over 3x3 of weight^2
__device__ float g_wT[CIN * 9 * COUT];   // weight transposed to [ci][k][co]
__device__ float g_demod[BB * COUT];

// ---------------------------------------------------------------------------
// s[b,ci] = style[b,:] . w_mod[ci,:] + b_mod[ci]   (one warp per output)
// ---------------------------------------------------------------------------
__global__ void mod_kernel(const float* __restrict__ style,
                           const float* __restrict__ w_mod,
                           const float* __restrict__ b_mod) {
    int warp = (blockIdx.x * blockDim.x + threadIdx.x) >> 5;
    int lane = threadIdx.x & 31;
    if (warp >= BB * CIN) return;
    int b = warp >> 9, ci = warp & 511;
    const float* st = style + b * SS;
    const float* wm = w_mod + ci * SS;
    float sum = 0.f;
    #pragma unroll 4
    for (int j = lane; j < SS; j += 32) sum += st[j] * wm[j];
    #pragma unroll
    for (int o = 16; o; o >>= 1) sum += __shfl_xor_sync(0xffffffffu, sum, o);
    if (lane == 0) g_s[warp] = sum + b_mod[ci];
}

// ---------------------------------------------------------------------------
// Transpose weight (co,ci,3,3) -> wT[ci][k][co]; also wsq[co,ci] = sum_k w^2
// ---------------------------------------------------------------------------
__global__ void wt_kernel(const float* __restrict__ weight) {
    int idx = blockIdx.x * blockDim.x + threadIdx.x;
    if (idx >= COUT * CIN) return;
    int co = idx & 511, ci = idx >> 9;
    const float* wp = weight + ((size_t)co * CIN + ci) * 9;
    float sq = 0.f;
    #pragma unroll
    for (int k = 0; k < 9; k++) {
        float v = wp[k];
        g_wT[((size_t)ci * 9 + k) * COUT + co] = v;
        sq += v * v;
    }
    g_wsq[co * CIN + ci] = sq;
}

// ---------------------------------------------------------------------------
// demod[b,co] = rsqrt( sum_ci s[b,ci]^2 * wsq[co,ci] + eps )
// ---------------------------------------------------------------------------
__global__ void demod_kernel() {
    int warp = (blockIdx.x * blockDim.x + threadIdx.x) >> 5;
    int lane = threadIdx.x & 31;
    if (warp >= BB * COUT) return;
    int b = warp >> 9, co = warp & 511;
    float sum = 0.f;
    #pragma unroll 4
    for (int j = lane; j < CIN; j += 32) {
        float sv = g_s[b * CIN + j];
        sum += sv * sv * g_wsq[co * CIN + j];
    }
    #pragma unroll
    for (int o = 16; o; o >>= 1) sum += __shfl_xor_sync(0xffffffffu, sum, o);
    if (lane == 0) g_demod[warp] = rsqrtf(sum + 1e-8f);
}

// ---------------------------------------------------------------------------
// Conv: shared weights, input scaled by s[b,ci] at smem fill, output scaled
// by demod[b,co]. Block = 64 co x 16x16 px, 512 threads.
// Thread tile = 4 co-pairs (f32x2) x 4 px. fma.rn.f32x2 for 2x fp32 rate.
// ---------------------------------------------------------------------------
__global__ void __launch_bounds__(512, 1)
conv_kernel(const float* __restrict__ x, float* __restrict__ out) {
    __shared__ __align__(16) float xs[CCH][TILE + 2][XSTR];
    __shared__ __align__(16) float ws[CCH][9][COB];

    int tile = blockIdx.x;               // 0..15 (4x4 spatial tiles)
    int tx = (tile & 3) * TILE;
    int ty = (tile >> 2) * TILE;
    int coBase = blockIdx.y * COB;
    int b = blockIdx.z;

    int tid = threadIdx.x;
    int pxg = tid & 3;                   // 4 pixel-column groups
    int py  = (tid >> 2) & 15;           // 16 rows
    int cog = tid >> 6;                  // 8 co groups of 8
    int px  = pxg << 2;

    unsigned long long acc2[4][4];       // [co-pair][px], each = 2 packed fp32
    #pragma unroll
    for (int c = 0; c < 4; c++)
        #pragma unroll
        for (int p = 0; p < 4; p++) acc2[c][p] = 0ull;

    const float* xb = x + (size_t)b * CIN * HH * WW;
    const float* sb = g_s + b * CIN;

    for (int ci0 = 0; ci0 < CIN; ci0 += CCH) {
        // --- fill x tile (with halo), scaling by s[b,ci] on the way in ---
        #pragma unroll 1
        for (int idx = tid; idx < CCH * 18 * 18; idx += 512) {
            int ci = idx / 324; int r = idx - ci * 324;
            int ly = r / 18, lx = r - ly * 18;
            int gy = ty + ly - 1, gx = tx + lx - 1;
            float v = 0.f;
            if (((unsigned)gy < 64u) & ((unsigned)gx < 64u))
                v = xb[(size_t)(ci0 + ci) * 4096 + (gy << 6) + gx] * sb[ci0 + ci];
            xs[ci][ly][lx] = v;
        }
        // --- fill weight tile, coalesced from pre-transposed wT ---
        #pragma unroll 1
        for (int idx = tid; idx < CCH * 9 * COB; idx += 512) {
            int ci = idx / 576; int r = idx - ci * 576;
            int k = r >> 6; int co = r & 63;
            ws[ci][k][co] = g_wT[((size_t)(ci0 + ci) * 9 + k) * COUT + coBase + co];
        }
        __syncthreads();

        #pragma unroll
        for (int ci = 0; ci < CCH; ci++) {
            #pragma unroll
            for (int dy = 0; dy < 3; dy++) {
                // 6 consecutive x values cover all dx shifts for 4 pixels
                unsigned long long xp[6];
                #pragma unroll
                for (int i = 0; i < 6; i++) {
                    float xv = xs[ci][py + dy][px + i];
                    unsigned long long pr;
                    asm("mov.b64 %0, {%1, %1};" : "=l"(pr) : "f"(xv));
                    xp[i] = pr;
                }
                #pragma unroll
                for (int dx = 0; dx < 3; dx++) {
                    int kk = dy * 3 + dx;
                    #pragma unroll
                    for (int c = 0; c < 4; c++) {
                        // aligned 8B pair of adjacent co weights (warp-uniform -> broadcast)
                        unsigned long long wp =
                            *(const unsigned long long*)&ws[ci][kk][(cog << 3) + (c << 1)];
                        #pragma unroll
                        for (int p = 0; p < 4; p++)
                            asm("fma.rn.f32x2 %0, %1, %2, %0;"
                                : "+l"(acc2[c][p]) : "l"(wp), "l"(xp[p + dx]));
                    }
                }
            }
        }
        __syncthreads();
    }

    // --- epilogue: unpack, scale by demod, vectorized stores ---
    #pragma unroll
    for (int c = 0; c < 4; c++) {
        int co0 = coBase + (cog << 3) + (c << 1);
        float d0 = g_demod[b * COUT + co0];
        float d1 = g_demod[b * COUT + co0 + 1];
        float o0[4], o1[4];
        #pragma unroll
        for (int p = 0; p < 4; p++) {
            float lo, hi;
            asm("mov.b64 {%0, %1}, %2;" : "=f"(lo), "=f"(hi) : "l"(acc2[c][p]));
            o0[p] = lo * d0;
            o1[p] = hi * d1;
        }
        size_t base0 = (((size_t)b * COUT + co0) * HH + ty + py) * WW + tx + px;
        *(float4*)&out[base0] = make_float4(o0[0], o0[1], o0[2], o0[3]);
        *(float4*)&out[base0 + (size_t)HH * WW] = make_float4(o1[0], o1[1], o1[2], o1[3]);
    }
}

// ---------------------------------------------------------------------------
extern "C" void kernel_launch(void* const* d_in, const int* in_sizes, int n_in,
                              void* d_out, int out_size) {
    const float* x      = (const float*)d_in[0];
    const float* style  = (const float*)d_in[1];
    const float* w_mod  = (const float*)d_in[2];
    const float* b_mod  = (const float*)d_in[3];
    const float* weight = (const float*)d_in[4];
    float* out = (float*)d_out;

    mod_kernel<<<512, 256>>>(style, w_mod, b_mod);          // 4096 warps
    wt_kernel<<<(COUT * CIN + 255) / 256, 256>>>(weight);
    demod_kernel<<<512, 256>>>();                           // 4096 warps
    dim3 grid(16, COUT / COB, BB);                          // 1024 blocks
    conv_kernel<<<grid, 512>>>(x, out);
}

// round 4
// speedup vs baseline: 3.6009x; 3.6009x over previous
#include <cuda_runtime.h>
#include <cuda_bf16.h>
#include <cstdint>

#define CIN 512
#define COUT 512
#define HH 64
#define WW 64
#define BB 8
#define SS 512

#define M_TILE 128
#define N_TILE 256            // 4 output rows x 64 cols
#define KC 32                 // K per chunk
#define NTAPS 9
#define NCHUNK (NTAPS * (512 / KC))   // 144
#define NSTAGE 3
#define ROWF 36               // padded floats per smem row (bank = lane)
#define STG_F ((M_TILE + N_TILE) * ROWF)    // 13824 floats / stage
#define SMEM_BYTES (NSTAGE * STG_F * 4)     // 165888

// ---------------------------------------------------------------------------
__device__ float g_s[BB * CIN];
__device__ float g_wsq[COUT * CIN];
__device__ float g_demod[BB * COUT];
__device__ float g_A[(size_t)NTAPS * COUT * CIN];          // tf32 weights, 9.4MB
__device__ float g_X[(size_t)BB * 66 * 66 * CIN];          // tf32 padded mod x, 71MB

__device__ __forceinline__ uint32_t smem_u32(const void* p) {
    uint32_t a;
    asm("{ .reg .u64 t; cvta.to.shared.u64 t, %1; cvt.u32.u64 %0, t; }" : "=r"(a) : "l"(p));
    return a;
}
__device__ __forceinline__ void cp16(uint32_t dst, const void* src) {
    asm volatile("cp.async.cg.shared.global [%0], [%1], 16;" :: "r"(dst), "l"(src));
}
__device__ __forceinline__ uint32_t f2tf32(float v) {
    uint32_t u;
    asm("cvt.rna.tf32.f32 %0, %1;" : "=r"(u) : "f"(v));
    return u;
}
__device__ __forceinline__ void mma_tf32(float* d, const uint32_t* a, const uint32_t* b) {
    asm volatile(
        "mma.sync.aligned.m16n8k8.row.col.f32.tf32.tf32.f32 "
        "{%0,%1,%2,%3}, {%4,%5,%6,%7}, {%8,%9}, {%0,%1,%2,%3};"
        : "+f"(d[0]), "+f"(d[1]), "+f"(d[2]), "+f"(d[3])
        : "r"(a[0]), "r"(a[1]), "r"(a[2]), "r"(a[3]), "r"(b[0]), "r"(b[1]));
}

// ---------------------------------------------------------------------------
// prep kernels
// ---------------------------------------------------------------------------
__global__ void mod_kernel(const float* __restrict__ style,
                           const float* __restrict__ w_mod,
                           const float* __restrict__ b_mod) {
    int warp = (blockIdx.x * blockDim.x + threadIdx.x) >> 5;
    int lane = threadIdx.x & 31;
    if (warp >= BB * CIN) return;
    int b = warp >> 9, ci = warp & 511;
    const float* st = style + b * SS;
    const float* wm = w_mod + ci * SS;
    float sum = 0.f;
    #pragma unroll 4
    for (int j = lane; j < SS; j += 32) sum += st[j] * wm[j];
    #pragma unroll
    for (int o = 16; o; o >>= 1) sum += __shfl_xor_sync(0xffffffffu, sum, o);
    if (lane == 0) g_s[warp] = sum + b_mod[ci];
}

__global__ void wprep_kernel(const float* __restrict__ weight) {
    int idx = blockIdx.x * blockDim.x + threadIdx.x;
    if (idx >= COUT * CIN) return;
    int co = idx >> 9, ci = idx & 511;
    const float* wp = weight + ((size_t)co * CIN + ci) * 9;
    uint32_t* gA = (uint32_t*)g_A;
    float sq = 0.f;
    #pragma unroll
    for (int t = 0; t < 9; t++) {
        float v = wp[t];
        sq += v * v;
        gA[((size_t)t * COUT + co) * CIN + ci] = f2tf32(v);
    }
    g_wsq[co * CIN + ci] = sq;
}

__global__ void demod_kernel() {
    int warp = (blockIdx.x * blockDim.x + threadIdx.x) >> 5;
    int lane = threadIdx.x & 31;
    if (warp >= BB * COUT) return;
    int b = warp >> 9, co = warp & 511;
    float sum = 0.f;
    #pragma unroll 4
    for (int j = lane; j < CIN; j += 32) {
        float sv = g_s[b * CIN + j];
        sum += sv * sv * g_wsq[co * CIN + j];
    }
    #pragma unroll
    for (int o = 16; o; o >>= 1) sum += __shfl_xor_sync(0xffffffffu, sum, o);
    if (lane == 0) g_demod[warp] = rsqrtf(sum + 1e-8f);
}

// padded modulated tf32 input: g_X[b][y:66][x:66][ci:512]
__global__ void xprep_kernel(const float* __restrict__ x) {
    int y = blockIdx.x;        // 0..65
    int b = blockIdx.y;
    int tid = threadIdx.x;     // 512
    int cig = tid >> 6, lx = tid & 63;
    __shared__ float xs[8][67];
    bool interior = (y >= 1 && y <= 64);
    uint32_t* gX = (uint32_t*)g_X;
    for (int ci0 = 0; ci0 < CIN; ci0 += 8) {
        int ci = ci0 + cig;
        float v = 0.f;
        if (interior)
            v = x[((size_t)(b * CIN + ci) * HH + (y - 1)) * WW + lx] * g_s[b * CIN + ci];
        xs[cig][lx + 1] = v;
        if (lx == 0) { xs[cig][0] = 0.f; xs[cig][65] = 0.f; }
        __syncthreads();
        #pragma unroll
        for (int idx = tid; idx < 528; idx += 512) {
            int xx = idx >> 3, c = idx & 7;
            gX[(((size_t)b * 66 + y) * 66 + xx) * CIN + ci0 + c] = f2tf32(xs[c][xx]);
        }
        __syncthreads();
    }
}

// ---------------------------------------------------------------------------
// GEMM: out[b,co,p] = demod[b,co] * sum_{tap,ci} A[tap][co][ci] * X[b][py+dy][px+dx][ci]
// ---------------------------------------------------------------------------
__global__ void __launch_bounds__(512, 1)
gemm_kernel(float* __restrict__ out) {
    extern __shared__ uint32_t smem[];
    uint32_t sb = smem_u32(smem);

    int tid = threadIdx.x;
    int wid = tid >> 5, lane = tid & 31;
    int wm = wid >> 3, wn = wid & 7;          // 2 x 8 warp grid
    int tg = lane >> 2, tr = lane & 3;

    int pt = blockIdx.x;                      // 16 pixel tiles (4 rows each)
    int cobase = blockIdx.y * M_TILE;         // 4 co tiles
    int b = blockIdx.z;
    int y0 = pt * 4;                          // first output row of tile

    const uint32_t* gA = (const uint32_t*)g_A;
    const uint32_t* gX = (const uint32_t*)g_X;

    float acc[4][4][4];
    #pragma unroll
    for (int i = 0; i < 4; i++)
        #pragma unroll
        for (int j = 0; j < 4; j++)
            #pragma unroll
            for (int q = 0; q < 4; q++) acc[i][j][q] = 0.f;

    // ---- chunk loader (cp.async, 6 x 16B per thread) ----
    auto load_chunk = [&](int c, int s) {
        int tap = c >> 4, kc = c & 15, k0 = kc * KC;
        int dy = tap / 3, dx = tap - dy * 3;
        uint32_t smA = sb + s * (STG_F * 4);
        uint32_t smB = smA + M_TILE * ROWF * 4;
        #pragma unroll
        for (int o = 0; o < 2; o++) {
            int lin = o * 512 + tid;
            int j = lin & 7, r = lin >> 3;
            cp16(smA + r * (ROWF * 4) + j * 16,
                 gA + ((size_t)(tap * COUT + cobase + r)) * CIN + k0 + j * 4);
        }
        #pragma unroll
        for (int o = 0; o < 4; o++) {
            int lin = o * 512 + tid;
            int j = lin & 7, p = lin >> 3;
            int ry = p >> 6, col = p & 63;
            cp16(smB + p * (ROWF * 4) + j * 16,
                 gX + (((size_t)b * 66 + y0 + ry + dy) * 66 + col + dx) * CIN + k0 + j * 4);
        }
    };

    // prologue: fill all stages
    #pragma unroll
    for (int c = 0; c < NSTAGE; c++) {
        load_chunk(c, c);
        asm volatile("cp.async.commit_group;");
    }

    for (int c = 0; c < NCHUNK; c++) {
        int s = c % NSTAGE;
        asm volatile("cp.async.wait_group %0;" :: "n"(NSTAGE - 1));
        __syncthreads();

        const uint32_t* As = smem + s * STG_F;
        const uint32_t* Bs = As + M_TILE * ROWF;

        #pragma unroll
        for (int k8 = 0; k8 < 4; k8++) {
            int kb = k8 * 8 + tr;
            uint32_t a[4][4];
            #pragma unroll
            for (int i = 0; i < 4; i++) {
                int r = wm * 64 + i * 16 + tg;
                a[i][0] = As[r * ROWF + kb];
                a[i][1] = As[(r + 8) * ROWF + kb];
                a[i][2] = As[r * ROWF + kb + 4];
                a[i][3] = As[(r + 8) * ROWF + kb + 4];
            }
            uint32_t bf[4][2];
            #pragma unroll
            for (int j = 0; j < 4; j++) {
                int p = wn * 32 + j * 8 + tg;
                bf[j][0] = Bs[p * ROWF + kb];
                bf[j][1] = Bs[p * ROWF + kb + 4];
            }
            #pragma unroll
            for (int i = 0; i < 4; i++)
                #pragma unroll
                for (int j = 0; j < 4; j++)
                    mma_tf32(acc[i][j], a[i], bf[j]);
        }

        __syncthreads();
        if (c + NSTAGE < NCHUNK) load_chunk(c + NSTAGE, s);
        asm volatile("cp.async.commit_group;");
    }

    // ---- epilogue: demod scale + float2 stores ----
    int pxbase = pt * N_TILE;
    #pragma unroll
    for (int i = 0; i < 4; i++) {
        int co = cobase + wm * 64 + i * 16 + tg;
        float d0 = g_demod[b * COUT + co];
        float d1 = g_demod[b * COUT + co + 8];
        float* o0 = out + ((size_t)(b * COUT + co)) * (HH * WW) + pxbase;
        float* o1 = o0 + (size_t)8 * HH * WW;
        #pragma unroll
        for (int j = 0; j < 4; j++) {
            int p = wn * 32 + j * 8 + tr * 2;
            float2 v0 = make_float2(acc[i][j][0] * d0, acc[i][j][1] * d0);
            float2 v1 = make_float2(acc[i][j][2] * d1, acc[i][j][3] * d1);
            *(float2*)(o0 + p) = v0;
            *(float2*)(o1 + p) = v1;
        }
    }
}

// ---------------------------------------------------------------------------
extern "C" void kernel_launch(void* const* d_in, const int* in_sizes, int n_in,
                              void* d_out, int out_size) {
    const float* x      = (const float*)d_in[0];
    const float* style  = (const float*)d_in[1];
    const float* w_mod  = (const float*)d_in[2];
    const float* b_mod  = (const float*)d_in[3];
    const float* weight = (const float*)d_in[4];
    float* out = (float*)d_out;

    mod_kernel<<<512, 256>>>(style, w_mod, b_mod);
    wprep_kernel<<<(COUT * CIN + 255) / 256, 256>>>(weight);
    demod_kernel<<<512, 256>>>();
    xprep_kernel<<<dim3(66, BB), 512>>>(x);

    cudaFuncSetAttribute(gemm_kernel, cudaFuncAttributeMaxDynamicSharedMemorySize, SMEM_BYTES);
    gemm_kernel<<<dim3(16, COUT / M_TILE, BB), 512, SMEM_BYTES>>>(out);
}

// round 5
// speedup vs baseline: 9.6201x; 2.6716x over previous
#include <cuda_runtime.h>
#include <cuda.h>
#include <cuda_fp16.h>
#include <cstdint>

#define CIN 512
#define COUT 512
#define HH 64
#define WW 64
#define BB 8
#define SS 512

#define M_TILE 128
#define N_TILE 256             // 4 output rows x 64 cols
#define KC 64                  // halves per chunk -> 128B rows (SW128)
#define NTAPS 9
#define NCHUNK (NTAPS * (512 / KC))     // 72
#define NSTAGE 4
#define A_BYTES (M_TILE * 128)          // 16KB
#define B_BYTES (N_TILE * 128)          // 32KB
#define STAGE_BYTES (A_BYTES + B_BYTES) // 48KB
#define SM_TILES 1024
#define SMEM_BYTES (SM_TILES + NSTAGE * STAGE_BYTES)

// ---------------------------------------------------------------------------
__device__ float  g_s[BB * CIN];
__device__ float  g_wsq[COUT * CIN];
__device__ float  g_demod[BB * COUT];
__device__ __half g_A[(size_t)NTAPS * COUT * CIN];      // fp16 weights (4.7MB)
__device__ __half g_X[(size_t)BB * 66 * 66 * CIN];      // fp16 padded mod x (36MB)

__device__ __forceinline__ uint32_t smem_u32(const void* p) {
    uint32_t a;
    asm("{ .reg .u64 t; cvta.to.shared.u64 t, %1; cvt.u32.u64 %0, t; }" : "=r"(a) : "l"(p));
    return a;
}
__device__ __forceinline__ void mbar_init(uint32_t m, uint32_t cnt) {
    asm volatile("mbarrier.init.shared.b64 [%0], %1;" :: "r"(m), "r"(cnt) : "memory");
}
__device__ __forceinline__ void mbar_arrive(uint32_t m) {
    asm volatile("mbarrier.arrive.shared.b64 _, [%0];" :: "r"(m) : "memory");
}
__device__ __forceinline__ void mbar_expect_tx(uint32_t m, uint32_t bytes) {
    asm volatile("mbarrier.arrive.expect_tx.shared.b64 _, [%0], %1;" :: "r"(m), "r"(bytes) : "memory");
}
__device__ __forceinline__ void mbar_wait(uint32_t m, uint32_t parity) {
    asm volatile(
        "{\n\t.reg .pred P;\n\t"
        "W_%=:\n\t"
        "mbarrier.try_wait.parity.acquire.cta.shared::cta.b64 P, [%0], %1, 0x989680;\n\t"
        "@P bra.uni D_%=;\n\t"
        "bra.uni W_%=;\n\t"
        "D_%=:\n\t}"
        :: "r"(m), "r"(parity) : "memory");
}
__device__ __forceinline__ void tma_load_3d(uint32_t dst, const void* map,
                                            int c0, int c1, int c2, uint32_t mbar) {
    asm volatile(
        "cp.async.bulk.tensor.3d.shared::cta.global.tile.mbarrier::complete_tx::bytes "
        "[%0], [%1, {%2, %3, %4}], [%5];"
        :: "r"(dst), "l"(map), "r"(c0), "r"(c1), "r"(c2), "r"(mbar) : "memory");
}
__device__ __forceinline__ void tma_load_4d(uint32_t dst, const void* map,
                                            int c0, int c1, int c2, int c3, uint32_t mbar) {
    asm volatile(
        "cp.async.bulk.tensor.4d.shared::cta.global.tile.mbarrier::complete_tx::bytes "
        "[%0], [%1, {%2, %3, %4, %5}], [%6];"
        :: "r"(dst), "l"(map), "r"(c0), "r"(c1), "r"(c2), "r"(c3), "r"(mbar) : "memory");
}
__device__ __forceinline__ void mma_f16(float* d, const uint32_t* a, const uint32_t* b) {
    asm volatile(
        "mma.sync.aligned.m16n8k16.row.col.f32.f16.f16.f32 "
        "{%0,%1,%2,%3}, {%4,%5,%6,%7}, {%8,%9}, {%0,%1,%2,%3};"
        : "+f"(d[0]), "+f"(d[1]), "+f"(d[2]), "+f"(d[3])
        : "r"(a[0]), "r"(a[1]), "r"(a[2]), "r"(a[3]), "r"(b[0]), "r"(b[1]));
}

// ---------------------------------------------------------------------------
// prep kernel 1: mod (blocks 0..511) + wprep (blocks 512..1535)
// ---------------------------------------------------------------------------
__global__ void prep1_kernel(const float* __restrict__ style,
                             const float* __restrict__ w_mod,
                             const float* __restrict__ b_mod,
                             const float* __restrict__ weight) {
    if (blockIdx.x < 512) {
        int warp = (blockIdx.x * 256 + threadIdx.x) >> 5;
        int lane = threadIdx.x & 31;
        int b = warp >> 9, ci = warp & 511;
        const float* st = style + b * SS;
        const float* wm = w_mod + ci * SS;
        float sum = 0.f;
        #pragma unroll 4
        for (int j = lane; j < SS; j += 32) sum += st[j] * wm[j];
        #pragma unroll
        for (int o = 16; o; o >>= 1) sum += __shfl_xor_sync(0xffffffffu, sum, o);
        if (lane == 0) g_s[warp] = sum + b_mod[ci];
    } else {
        int idx = (blockIdx.x - 512) * 256 + threadIdx.x;   // 0..262143
        int co = idx >> 9, ci = idx & 511;
        const float* wp = weight + ((size_t)co * CIN + ci) * 9;
        float sq = 0.f;
        #pragma unroll
        for (int t = 0; t < 9; t++) {
            float v = wp[t];
            sq += v * v;
            g_A[((size_t)t * COUT + co) * CIN + ci] = __float2half(v);
        }
        g_wsq[co * CIN + ci] = sq;
    }
}

// ---------------------------------------------------------------------------
// prep kernel 2: demod (blocks 0..255) + xprep (blocks 256..783)
// ---------------------------------------------------------------------------
__global__ void prep2_kernel(const float* __restrict__ x) {
    if (blockIdx.x < 256) {
        int warp = (blockIdx.x * 512 + threadIdx.x) >> 5;
        int lane = threadIdx.x & 31;
        int b = warp >> 9, co = warp & 511;
        float sum = 0.f;
        #pragma unroll 4
        for (int j = lane; j < CIN; j += 32) {
            float sv = g_s[b * CIN + j];
            sum += sv * sv * g_wsq[co * CIN + j];
        }
        #pragma unroll
        for (int o = 16; o; o >>= 1) sum += __shfl_xor_sync(0xffffffffu, sum, o);
        if (lane == 0) g_demod[warp] = rsqrtf(sum + 1e-8f);
    } else {
        int blk = blockIdx.x - 256;       // 0..527
        int y = blk % 66, b = blk / 66;
        int tid = threadIdx.x;            // 512
        int cig = tid >> 6, lx = tid & 63;
        __shared__ float xs[8][67];
        bool interior = (y >= 1 && y <= 64);
        for (int ci0 = 0; ci0 < CIN; ci0 += 8) {
            int ci = ci0 + cig;
            float v = 0.f;
            if (interior)
                v = x[((size_t)(b * CIN + ci) * HH + (y - 1)) * WW + lx] * g_s[b * CIN + ci];
            xs[cig][lx + 1] = v;
            if (lx == 0) { xs[cig][0] = 0.f; xs[cig][65] = 0.f; }
            __syncthreads();
            #pragma unroll
            for (int idx = tid; idx < 528; idx += 512) {
                int xx = idx >> 3, c = idx & 7;
                g_X[(((size_t)b * 66 + y) * 66 + xx) * CIN + ci0 + c] = __float2half(xs[c][xx]);
            }
            __syncthreads();
        }
    }
}

// ---------------------------------------------------------------------------
// GEMM: fp16 m16n8k16, TMA producer warp + 8 consumer warps (64x64 each).
// smem tiles SW128-swizzled by TMA; row&7 == tg for every fragment row, so
// swizzled col = (ks*32 + tr*4) ^ (tg<<4) and all LDS are conflict-free.
// ---------------------------------------------------------------------------
__global__ void __launch_bounds__(288, 1)
gemm_kernel(const __grid_constant__ CUtensorMap tmA,
            const __grid_constant__ CUtensorMap tmB,
            float* __restrict__ out) {
    extern __shared__ char smem[];
    uint32_t sb = smem_u32(smem);
    int tid = threadIdx.x;
    int wid = tid >> 5, lane = tid & 31;
    int tg = lane >> 2, tr = lane & 3;

    int pt = blockIdx.x;                 // 16 pixel tiles (4 rows x 64)
    int cobase = blockIdx.y * M_TILE;    // 4 co tiles
    int b = blockIdx.z;
    int y0 = pt * 4;

    uint32_t mb_full = sb;               // 4 x 8B
    uint32_t mb_cons = sb + 64;

    if (tid == 0) {
        #pragma unroll
        for (int s = 0; s < NSTAGE; s++) {
            mbar_init(mb_full + s * 8, 1);
            mbar_init(mb_cons + s * 8, 8);
        }
        asm volatile("fence.proxy.async.shared::cta;" ::: "memory");
    }
    __syncthreads();

    // ---- producer: warp 8, lane 0 ----
    if (wid == 8) {
        if (lane == 0) {
            for (int c = 0; c < NCHUNK; c++) {
                int s = c & 3;
                if (c >= NSTAGE) mbar_wait(mb_cons + s * 8, ((c - NSTAGE) >> 2) & 1);
                int tap = c >> 3, kc = c & 7, k0 = kc * KC;
                int dy = tap / 3, dx = tap - dy * 3;
                uint32_t smA = sb + SM_TILES + s * STAGE_BYTES;
                uint32_t smB = smA + A_BYTES;
                mbar_expect_tx(mb_full + s * 8, STAGE_BYTES);
                tma_load_3d(smA, &tmA, k0, cobase, tap, mb_full + s * 8);
                tma_load_4d(smB, &tmB, k0, dx, y0 + dy, b, mb_full + s * 8);
            }
        }
        return;
    }

    // ---- consumers: warps 0..7, warp tile 64(co) x 64(px) ----
    int wm = wid >> 2, wn = wid & 3;
    float acc[4][8][4];
    #pragma unroll
    for (int i = 0; i < 4; i++)
        #pragma unroll
        for (int j = 0; j < 8; j++)
            #pragma unroll
            for (int q = 0; q < 4; q++) acc[i][j][q] = 0.f;

    for (int c = 0; c < NCHUNK; c++) {
        int s = c & 3;
        mbar_wait(mb_full + s * 8, (c >> 2) & 1);
        const char* As = smem + SM_TILES + s * STAGE_BYTES;
        const char* Bs = As + A_BYTES;
        const char* pa0 = As + (wm * 64 + tg) * 128;
        const char* pb0 = Bs + (wn * 64 + tg) * 128;

        #pragma unroll
        for (int ks = 0; ks < 4; ks++) {
            int c0 = (ks * 32 + tr * 4) ^ (tg << 4);
            int c1 = c0 ^ 16;
            uint32_t a[4][4];
            #pragma unroll
            for (int i = 0; i < 4; i++) {
                const char* pa = pa0 + i * (16 * 128);
                a[i][0] = *(const uint32_t*)(pa + c0);
                a[i][1] = *(const uint32_t*)(pa + 1024 + c0);
                a[i][2] = *(const uint32_t*)(pa + c1);
                a[i][3] = *(const uint32_t*)(pa + 1024 + c1);
            }
            uint32_t bt[8][2];
            #pragma unroll
            for (int j = 0; j < 8; j++) {
                bt[j][0] = *(const uint32_t*)(pb0 + j * 1024 + c0);
                bt[j][1] = *(const uint32_t*)(pb0 + j * 1024 + c1);
            }
            #pragma unroll
            for (int i = 0; i < 4; i++)
                #pragma unroll
                for (int j = 0; j < 8; j++)
                    mma_f16(acc[i][j], a[i], bt[j]);
        }
        __syncwarp();
        if (lane == 0) mbar_arrive(mb_cons + s * 8);
    }

    // ---- epilogue: demod scale + float2 stores ----
    #pragma unroll
    for (int i = 0; i < 4; i++) {
        int co = cobase + wm * 64 + i * 16 + tg;
        float d0 = g_demod[b * COUT + co];
        float d1 = g_demod[b * COUT + co + 8];
        float* o0 = out + ((size_t)(b * COUT + co)) * (HH * WW) + pt * 256;
        float* o1 = o0 + (size_t)8 * HH * WW;
        #pragma unroll
        for (int j = 0; j < 8; j++) {
            int p = wn * 64 + j * 8 + tr * 2;
            *(float2*)(o0 + p) = make_float2(acc[i][j][0] * d0, acc[i][j][1] * d0);
            *(float2*)(o1 + p) = make_float2(acc[i][j][2] * d1, acc[i][j][3] * d1);
        }
    }
}

// ---------------------------------------------------------------------------
extern "C" void kernel_launch(void* const* d_in, const int* in_sizes, int n_in,
                              void* d_out, int out_size) {
    const float* x      = (const float*)d_in[0];
    const float* style  = (const float*)d_in[1];
    const float* w_mod  = (const float*)d_in[2];
    const float* b_mod  = (const float*)d_in[3];
    const float* weight = (const float*)d_in[4];
    float* out = (float*)d_out;

    prep1_kernel<<<1536, 256>>>(style, w_mod, b_mod, weight);
    prep2_kernel<<<784, 512>>>(x);

    // tensor maps (host-side, capture-safe)
    typedef CUresult (*EncFn)(CUtensorMap*, CUtensorMapDataType, cuuint32_t, void*,
                              const cuuint64_t*, const cuuint64_t*, const cuuint32_t*,
                              const cuuint32_t*, CUtensorMapInterleave, CUtensorMapSwizzle,
                              CUtensorMapL2promotion, CUtensorMapFloatOOBfill);
    EncFn enc = nullptr;
    cudaDriverEntryPointQueryResult qr;
    cudaGetDriverEntryPoint("cuTensorMapEncodeTiled", (void**)&enc, cudaEnableDefault, &qr);

    void* pA = nullptr; void* pX = nullptr;
    cudaGetSymbolAddress(&pA, g_A);
    cudaGetSymbolAddress(&pX, g_X);

    static CUtensorMap tmA, tmB;
    {
        cuuint64_t dims[3]    = {CIN, COUT, NTAPS};
        cuuint64_t strides[2] = {(cuuint64_t)CIN * 2, (cuuint64_t)COUT * CIN * 2};
        cuuint32_t box[3]     = {KC, M_TILE, 1};
        cuuint32_t es[3]      = {1, 1, 1};
        enc(&tmA, CU_TENSOR_MAP_DATA_TYPE_FLOAT16, 3, pA, dims, strides, box, es,
            CU_TENSOR_MAP_INTERLEAVE_NONE, CU_TENSOR_MAP_SWIZZLE_128B,
            CU_TENSOR_MAP_L2_PROMOTION_L2_128B, CU_TENSOR_MAP_FLOAT_OOB_FILL_NONE);
    }
    {
        cuuint64_t dims[4]    = {CIN, 66, 66, BB};
        cuuint64_t strides[3] = {(cuuint64_t)CIN * 2, 66ull * CIN * 2, 66ull * 66 * CIN * 2};
        cuuint32_t box[4]     = {KC, 64, 4, 1};
        cuuint32_t es[4]      = {1, 1, 1, 1};
        enc(&tmB, CU_TENSOR_MAP_DATA_TYPE_FLOAT16, 4, pX, dims, strides, box, es,
            CU_TENSOR_MAP_INTERLEAVE_NONE, CU_TENSOR_MAP_SWIZZLE_128B,
            CU_TENSOR_MAP_L2_PROMOTION_L2_128B, CU_TENSOR_MAP_FLOAT_OOB_FILL_NONE);
    }

    cudaFuncSetAttribute(gemm_kernel, cudaFuncAttributeMaxDynamicSharedMemorySize, SMEM_BYTES);
    gemm_kernel<<<dim3(16, COUT / M_TILE, BB), 288, SMEM_BYTES>>>(tmA, tmB, out);
}

// round 6
// speedup vs baseline: 9.7991x; 1.0186x over previous
#include <cuda_runtime.h>
#include <cuda.h>
#include <cuda_fp16.h>
#include <cstdint>

#define CIN 512
#define COUT 512
#define HH 64
#define WW 64
#define BB 8
#define SS 512

#define M_TILE 128
#define N_TILE 256             // 4 output rows x 64 cols
#define KC 64                  // halves per chunk -> 128B rows (SW128)
#define NTAPS 9
#define NCHUNK (NTAPS * (512 / KC))     // 72
#define NSTAGE 4
#define A_BYTES (M_TILE * 128)          // 16KB
#define B_BYTES (N_TILE * 128)          // 32KB
#define STAGE_BYTES (A_BYTES + B_BYTES) // 48KB
#define SM_TILES 1024
#define SMEM_BYTES (SM_TILES + NSTAGE * STAGE_BYTES)

#define XP_ROW 514                      // xprep smem row stride (halves); odd word stride
#define XP_SMEM (66 * XP_ROW * 2)       // 67848 B

// ---------------------------------------------------------------------------
__device__ float  g_s[BB * CIN];
__device__ float  g_wsq[COUT * CIN];
__device__ float  g_demod[BB * COUT];
__device__ __half g_A[(size_t)NTAPS * COUT * CIN];      // fp16 weights (4.7MB)
__device__ __half g_X[(size_t)BB * 66 * 66 * CIN];      // fp16 padded mod x (36MB)

__device__ __forceinline__ uint32_t smem_u32(const void* p) {
    uint32_t a;
    asm("{ .reg .u64 t; cvta.to.shared.u64 t, %1; cvt.u32.u64 %0, t; }" : "=r"(a) : "l"(p));
    return a;
}
__device__ __forceinline__ void mbar_init(uint32_t m, uint32_t cnt) {
    asm volatile("mbarrier.init.shared.b64 [%0], %1;" :: "r"(m), "r"(cnt) : "memory");
}
__device__ __forceinline__ void mbar_arrive(uint32_t m) {
    asm volatile("mbarrier.arrive.shared.b64 _, [%0];" :: "r"(m) : "memory");
}
__device__ __forceinline__ void mbar_expect_tx(uint32_t m, uint32_t bytes) {
    asm volatile("mbarrier.arrive.expect_tx.shared.b64 _, [%0], %1;" :: "r"(m), "r"(bytes) : "memory");
}
__device__ __forceinline__ void mbar_wait(uint32_t m, uint32_t parity) {
    asm volatile(
        "{\n\t.reg .pred P;\n\t"
        "W_%=:\n\t"
        "mbarrier.try_wait.parity.acquire.cta.shared::cta.b64 P, [%0], %1, 0x989680;\n\t"
        "@P bra.uni D_%=;\n\t"
        "bra.uni W_%=;\n\t"
        "D_%=:\n\t}"
        :: "r"(m), "r"(parity) : "memory");
}
__device__ __forceinline__ void tma_load_3d(uint32_t dst, const void* map,
                                            int c0, int c1, int c2, uint32_t mbar) {
    asm volatile(
        "cp.async.bulk.tensor.3d.shared::cta.global.tile.mbarrier::complete_tx::bytes "
        "[%0], [%1, {%2, %3, %4}], [%5];"
        :: "r"(dst), "l"(map), "r"(c0), "r"(c1), "r"(c2), "r"(mbar) : "memory");
}
__device__ __forceinline__ void tma_load_4d(uint32_t dst, const void* map,
                                            int c0, int c1, int c2, int c3, uint32_t mbar) {
    asm volatile(
        "cp.async.bulk.tensor.4d.shared::cta.global.tile.mbarrier::complete_tx::bytes "
        "[%0], [%1, {%2, %3, %4, %5}], [%6];"
        :: "r"(dst), "l"(map), "r"(c0), "r"(c1), "r"(c2), "r"(c3), "r"(mbar) : "memory");
}
__device__ __forceinline__ void mma_f16(float* d, const uint32_t* a, uint32_t b0, uint32_t b1) {
    asm volatile(
        "mma.sync.aligned.m16n8k16.row.col.f32.f16.f16.f32 "
        "{%0,%1,%2,%3}, {%4,%5,%6,%7}, {%8,%9}, {%0,%1,%2,%3};"
        : "+f"(d[0]), "+f"(d[1]), "+f"(d[2]), "+f"(d[3])
        : "r"(a[0]), "r"(a[1]), "r"(a[2]), "r"(a[3]), "r"(b0), "r"(b1));
}
__device__ __forceinline__ void ldsm4(uint32_t* r, uint32_t addr) {
    asm volatile("ldmatrix.sync.aligned.m8n8.x4.shared.b16 {%0,%1,%2,%3}, [%4];"
        : "=r"(r[0]), "=r"(r[1]), "=r"(r[2]), "=r"(r[3]) : "r"(addr));
}

// ---------------------------------------------------------------------------
// prep kernel 1: mod (blocks 0..511) + wprep (blocks 512..1535)
// ---------------------------------------------------------------------------
__global__ void prep1_kernel(const float* __restrict__ style,
                             const float* __restrict__ w_mod,
                             const float* __restrict__ b_mod,
                             const float* __restrict__ weight) {
    if (blockIdx.x < 512) {
        int warp = (blockIdx.x * 256 + threadIdx.x) >> 5;
        int lane = threadIdx.x & 31;
        int b = warp >> 9, ci = warp & 511;
        const float* st = style + b * SS;
        const float* wm = w_mod + ci * SS;
        float sum = 0.f;
        #pragma unroll 4
        for (int j = lane; j < SS; j += 32) sum += st[j] * wm[j];
        #pragma unroll
        for (int o = 16; o; o >>= 1) sum += __shfl_xor_sync(0xffffffffu, sum, o);
        if (lane == 0) g_s[warp] = sum + b_mod[ci];
    } else {
        int idx = (blockIdx.x - 512) * 256 + threadIdx.x;   // 0..262143
        int co = idx >> 9, ci = idx & 511;
        const float* wp = weight + ((size_t)co * CIN + ci) * 9;
        float sq = 0.f;
        #pragma unroll
        for (int t = 0; t < 9; t++) {
            float v = wp[t];
            sq += v * v;
            g_A[((size_t)t * COUT + co) * CIN + ci] = __float2half(v);
        }
        g_wsq[co * CIN + ci] = sq;
    }
}

// ---------------------------------------------------------------------------
// prep kernel 2: demod (blocks 0..255) + xprep transpose (blocks 256..783)
// ---------------------------------------------------------------------------
__global__ void prep2_kernel(const float* __restrict__ x) {
    extern __shared__ __half sh[];     // [66][XP_ROW]
    if (blockIdx.x < 256) {
        int warp = (blockIdx.x * 512 + threadIdx.x) >> 5;
        int lane = threadIdx.x & 31;
        int b = warp >> 9, co = warp & 511;
        float sum = 0.f;
        #pragma unroll 4
        for (int j = lane; j < CIN; j += 32) {
            float sv = g_s[b * CIN + j];
            sum += sv * sv * g_wsq[co * CIN + j];
        }
        #pragma unroll
        for (int o = 16; o; o >>= 1) sum += __shfl_xor_sync(0xffffffffu, sum, o);
        if (lane == 0) g_demod[warp] = rsqrtf(sum + 1e-8f);
    } else {
        int blk = blockIdx.x - 256;       // 0..527
        int y = blk % 66, b = blk / 66;
        int tid = threadIdx.x;            // 512
        int wid = tid >> 5, lane = tid & 31;
        bool interior = (y >= 1 && y <= 64);
        // phase 1: coalesced reads of x rows; transpose into smem sh[xx][ci]
        #pragma unroll 1
        for (int r = 0; r < 32; r++) {
            int ci = r * 16 + wid;
            float sv = g_s[b * CIN + ci];
            float v0 = 0.f, v1 = 0.f;
            if (interior) {
                const float* xr = x + ((size_t)(b * CIN + ci) * HH + (y - 1)) * WW;
                v0 = xr[lane] * sv;
                v1 = xr[lane + 32] * sv;
            }
            sh[(1 + lane) * XP_ROW + ci]  = __float2half(v0);
            sh[(33 + lane) * XP_ROW + ci] = __float2half(v1);
            if (lane == 0) {
                sh[ci] = __half(0.f);                 // xx = 0
                sh[65 * XP_ROW + ci] = __half(0.f);   // xx = 65
            }
        }
        __syncthreads();
        // phase 2: coalesced 1KB-contiguous writes per xx
        __half* dst = g_X + ((size_t)b * 66 + y) * 66 * CIN;
        #pragma unroll 2
        for (int xx = 0; xx < 66; xx++)
            dst[(size_t)xx * CIN + tid] = sh[xx * XP_ROW + tid];
    }
}

// ---------------------------------------------------------------------------
// GEMM: fp16 m16n8k16 via ldmatrix.x4, TMA producer warp + 8 consumer warps.
// ---------------------------------------------------------------------------
__global__ void __launch_bounds__(288, 1)
gemm_kernel(const __grid_constant__ CUtensorMap tmA,
            const __grid_constant__ CUtensorMap tmB,
            float* __restrict__ out) {
    extern __shared__ char smem[];
    uint32_t sb = smem_u32(smem);
    int tid = threadIdx.x;
    int wid = tid >> 5, lane = tid & 31;
    int tg = lane >> 2, tr = lane & 3;

    int pt = blockIdx.x;                 // 16 pixel tiles (4 rows x 64)
    int cobase = blockIdx.y * M_TILE;    // 4 co tiles
    int b = blockIdx.z;
    int y0 = pt * 4;

    uint32_t mb_full = sb;               // 4 x 8B
    uint32_t mb_cons = sb + 64;

    if (tid == 0) {
        #pragma unroll
        for (int s = 0; s < NSTAGE; s++) {
            mbar_init(mb_full + s * 8, 1);
            mbar_init(mb_cons + s * 8, 8);
        }
        asm volatile("fence.proxy.async.shared::cta;" ::: "memory");
    }
    __syncthreads();

    // ---- producer: warp 8, lane 0 ----
    if (wid == 8) {
        if (lane == 0) {
            for (int c = 0; c < NCHUNK; c++) {
                int s = c & 3;
                if (c >= NSTAGE) mbar_wait(mb_cons + s * 8, ((c - NSTAGE) >> 2) & 1);
                int tap = c >> 3, kc = c & 7, k0 = kc * KC;
                int dy = tap / 3, dx = tap - dy * 3;
                uint32_t smA = sb + SM_TILES + s * STAGE_BYTES;
                uint32_t smB = smA + A_BYTES;
                mbar_expect_tx(mb_full + s * 8, STAGE_BYTES);
                tma_load_3d(smA, &tmA, k0, cobase, tap, mb_full + s * 8);
                tma_load_4d(smB, &tmB, k0, dx, y0 + dy, b, mb_full + s * 8);
            }
        }
        return;
    }

    // ---- consumers: warps 0..7, warp tile 64(co) x 64(px) ----
    int wm = wid >> 2, wn = wid & 3;
    int l7 = lane & 7;
    uint32_t swz = (uint32_t)l7 << 4;
    // ldmatrix lane->address mapping (non-trans for both operands):
    // A groups: (m0-7,k0)(m8-15,k0)(m0-7,k8)(m8-15,k8)
    uint32_t aRow = wm * 64 + l7 + ((lane & 8) ? 8 : 0);
    uint32_t aKoff = (lane & 16) ? 16u : 0u;
    // B groups: (n0-7,k0)(n0-7,k8)(n8-15,k0)(n8-15,k8)
    uint32_t bRow = wn * 64 + l7 + ((lane & 16) ? 8 : 0);
    uint32_t bKoff = (lane & 8) ? 16u : 0u;

    float acc[4][8][4];
    #pragma unroll
    for (int i = 0; i < 4; i++)
        #pragma unroll
        for (int j = 0; j < 8; j++)
            #pragma unroll
            for (int q = 0; q < 4; q++) acc[i][j][q] = 0.f;

    for (int c = 0; c < NCHUNK; c++) {
        int s = c & 3;
        mbar_wait(mb_full + s * 8, (c >> 2) & 1);
        uint32_t As = sb + SM_TILES + s * STAGE_BYTES;
        uint32_t Bs = As + A_BYTES;
        uint32_t aBase = As + aRow * 128;
        uint32_t bBase = Bs + bRow * 128;

        #pragma unroll
        for (int ks = 0; ks < 4; ks++) {
            uint32_t aCol = ((uint32_t)(ks * 32) + aKoff) ^ swz;
            uint32_t bCol = ((uint32_t)(ks * 32) + bKoff) ^ swz;
            uint32_t af[4][4];
            #pragma unroll
            for (int i = 0; i < 4; i++) ldsm4(af[i], aBase + i * 2048 + aCol);
            uint32_t bf[4][4];
            #pragma unroll
            for (int jp = 0; jp < 4; jp++) ldsm4(bf[jp], bBase + jp * 2048 + bCol);
            #pragma unroll
            for (int i = 0; i < 4; i++)
                #pragma unroll
                for (int j = 0; j < 8; j++)
                    mma_f16(acc[i][j], af[i], bf[j >> 1][(j & 1) * 2], bf[j >> 1][(j & 1) * 2 + 1]);
        }
        __syncwarp();
        if (lane == 0) mbar_arrive(mb_cons + s * 8);
    }

    // ---- epilogue: demod scale + float2 stores ----
    #pragma unroll
    for (int i = 0; i < 4; i++) {
        int co = cobase + wm * 64 + i * 16 + tg;
        float d0 = g_demod[b * COUT + co];
        float d1 = g_demod[b * COUT + co + 8];
        float* o0 = out + ((size_t)(b * COUT + co)) * (HH * WW) + pt * 256;
        float* o1 = o0 + (size_t)8 * HH * WW;
        #pragma unroll
        for (int j = 0; j < 8; j++) {
            int p = wn * 64 + j * 8 + tr * 2;
            *(float2*)(o0 + p) = make_float2(acc[i][j][0] * d0, acc[i][j][1] * d0);
            *(float2*)(o1 + p) = make_float2(acc[i][j][2] * d1, acc[i][j][3] * d1);
        }
    }
}

// ---------------------------------------------------------------------------
extern "C" void kernel_launch(void* const* d_in, const int* in_sizes, int n_in,
                              void* d_out, int out_size) {
    const float* x      = (const float*)d_in[0];
    const float* style  = (const float*)d_in[1];
    const float* w_mod  = (const float*)d_in[2];
    const float* b_mod  = (const float*)d_in[3];
    const float* weight = (const float*)d_in[4];
    float* out = (float*)d_out;

    prep1_kernel<<<1536, 256>>>(style, w_mod, b_mod, weight);
    cudaFuncSetAttribute(prep2_kernel, cudaFuncAttributeMaxDynamicSharedMemorySize, XP_SMEM);
    prep2_kernel<<<784, 512, XP_SMEM>>>(x);

    // tensor maps (host-side, capture-safe)
    typedef CUresult (*EncFn)(CUtensorMap*, CUtensorMapDataType, cuuint32_t, void*,
                              const cuuint64_t*, const cuuint64_t*, const cuuint32_t*,
                              const cuuint32_t*, CUtensorMapInterleave, CUtensorMapSwizzle,
                              CUtensorMapL2promotion, CUtensorMapFloatOOBfill);
    EncFn enc = nullptr;
    cudaDriverEntryPointQueryResult qr;
    cudaGetDriverEntryPoint("cuTensorMapEncodeTiled", (void**)&enc, cudaEnableDefault, &qr);

    void* pA = nullptr; void* pX = nullptr;
    cudaGetSymbolAddress(&pA, g_A);
    cudaGetSymbolAddress(&pX, g_X);

    static CUtensorMap tmA, tmB;
    {
        cuuint64_t dims[3]    = {CIN, COUT, NTAPS};
        cuuint64_t strides[2] = {(cuuint64_t)CIN * 2, (cuuint64_t)COUT * CIN * 2};
        cuuint32_t box[3]     = {KC, M_TILE, 1};
        cuuint32_t es[3]      = {1, 1, 1};
        enc(&tmA, CU_TENSOR_MAP_DATA_TYPE_FLOAT16, 3, pA, dims, strides, box, es,
            CU_TENSOR_MAP_INTERLEAVE_NONE, CU_TENSOR_MAP_SWIZZLE_128B,
            CU_TENSOR_MAP_L2_PROMOTION_L2_128B, CU_TENSOR_MAP_FLOAT_OOB_FILL_NONE);
    }
    {
        cuuint64_t dims[4]    = {CIN, 66, 66, BB};
        cuuint64_t strides[3] = {(cuuint64_t)CIN * 2, 66ull * CIN * 2, 66ull * 66 * CIN * 2};
        cuuint32_t box[4]     = {KC, 64, 4, 1};
        cuuint32_t es[4]      = {1, 1, 1, 1};
        enc(&tmB, CU_TENSOR_MAP_DATA_TYPE_FLOAT16, 4, pX, dims, strides, box, es,
            CU_TENSOR_MAP_INTERLEAVE_NONE, CU_TENSOR_MAP_SWIZZLE_128B,
            CU_TENSOR_MAP_L2_PROMOTION_L2_128B, CU_TENSOR_MAP_FLOAT_OOB_FILL_NONE);
    }

    cudaFuncSetAttribute(gemm_kernel, cudaFuncAttributeMaxDynamicSharedMemorySize, SMEM_BYTES);
    gemm_kernel<<<dim3(16, COUT / M_TILE, BB), 288, SMEM_BYTES>>>(tmA, tmB, out);
}